// round 4
// baseline (speedup 1.0000x reference)
#include <cuda_runtime.h>

// out[b,o,h,w] = x[b,o,h,w] + bias[o],  bias[o] = -0.1f * sum_{c,kh,kw} |W2[o,c,kh,kw]|
//
// Derivation: adder2d outputs -sum|patch - w| <= 0 everywhere (strictly < 0 for
// continuous random inputs), so relu(adder2d(x, W1)) is exactly 0.0f everywhere.
// adder2d on an all-zero input (zero padding included) yields the per-channel
// constant -sum|W2[o]| at every spatial position. Hence
//   reference(x, W1, W2) == x - 0.1 * sum|W2[o,:,:,:]|.
//
// Single fused kernel: each 256-thread block covers 256 contiguous float4 of x
// (1024 floats), which lies entirely within one (b,o) slab of 4096 floats, so the
// whole block shares one output channel o. The block redundantly reduces the 576
// |W2[o]| values (L2-hot, 2.3 KB) while its x float4 load is in flight.

__global__ __launch_bounds__(256) void fused_resblock_kernel(
    const float* __restrict__ x,
    const float* __restrict__ W2,
    float* __restrict__ out,
    int n4)
{
    const int t   = threadIdx.x;
    const int bid = blockIdx.x;
    const int i   = bid * 256 + t;          // float4 index
    // layout [B=8][O=64][H=64][W=64]: slab = 4096 floats = 1024 float4 per (b,o)
    const int o   = (bid >> 2) & 63;        // 4 blocks per slab, same o per block

    // issue payload load early (overlaps the bias reduction below)
    float4 v = make_float4(0.f, 0.f, 0.f, 0.f);
    if (i < n4) v = reinterpret_cast<const float4*>(x)[i];

    // block-redundant bias reduction: sum |W2[o, 0:576]|
    const float* w = W2 + o * 576;
    float s = fabsf(w[t]) + fabsf(w[t + 256]);
    if (t < 64) s += fabsf(w[t + 512]);
    #pragma unroll
    for (int d = 16; d > 0; d >>= 1)
        s += __shfl_xor_sync(0xFFFFFFFFu, s, d);

    __shared__ float warp_sum[8];
    if ((t & 31) == 0) warp_sum[t >> 5] = s;
    __syncthreads();

    const float total = warp_sum[0] + warp_sum[1] + warp_sum[2] + warp_sum[3]
                      + warp_sum[4] + warp_sum[5] + warp_sum[6] + warp_sum[7];
    const float b = -0.1f * total;

    v.x += b; v.y += b; v.z += b; v.w += b;
    if (i < n4) reinterpret_cast<float4*>(out)[i] = v;
}

extern "C" void kernel_launch(void* const* d_in, const int* in_sizes, int n_in,
                              void* d_out, int out_size) {
    const float* x  = (const float*)d_in[0];   // [8,64,64,64] float32
    // d_in[1] = W1 (unused: relu(adder2d(x, W1)) == 0 exactly)
    const float* W2 = (const float*)d_in[2];   // [64,64,3,3] float32
    float* out = (float*)d_out;

    const int n4     = out_size / 4;                 // 524288 float4
    const int blocks = (n4 + 255) / 256;             // 2048
    fused_resblock_kernel<<<blocks, 256>>>(x, W2, out, n4);
}